// round 3
// baseline (speedup 1.0000x reference)
#include <cuda_runtime.h>
#include <cuda_bf16.h>
#include <math.h>

// ---------------------------------------------------------------------------
// TransformerDecoder on GB300 — Round 1 fp32 baseline.
//
// Key reduction: softmax rows sum to 1 => head_out == Vv exactly; attention
// (Q,K,scores,softmax) is dead code. Each block is just two 768x768 GEMMs,
// an FFN (768->3072->768), residuals and two custom LayerNorms.
// ---------------------------------------------------------------------------

#define D_MODEL 768
#define HID     3072
#define VOCAB   8192
#define ROWS    4096          // B*S = 4*1024
#define NBLK    4

// Scratch (device globals; allocation is forbidden)
__device__ float g_X [ROWS * D_MODEL];      // current activations
__device__ float g_T1[ROWS * D_MODEL];      // V-proj output
__device__ float g_T2[ROWS * D_MODEL];      // residual-sum buffer
__device__ float g_H [ROWS * HID];          // FFN hidden
__device__ float g_Wv[NBLK * D_MODEL * D_MODEL]; // repacked Wv

// ---------------------------------------------------------------------------
// Repack Wv[i][h][d][e] ([NB,H,D,DK]) -> Wrp[i][d][h*64+e] ([NB,D,H*DK])
// ---------------------------------------------------------------------------
__global__ void repack_wv_k(const float* __restrict__ Wv, float* __restrict__ Wrp) {
    int idx = blockIdx.x * blockDim.x + threadIdx.x;
    const int per = D_MODEL * D_MODEL;
    if (idx >= NBLK * per) return;
    int i = idx / per;
    int r = idx % per;
    int d = r / D_MODEL;
    int j = r % D_MODEL;
    int h = j >> 6;          // j / 64
    int e = j & 63;          // j % 64
    Wrp[idx] = Wv[(((size_t)i * 12 + h) * D_MODEL + d) * 64 + e];
}

// ---------------------------------------------------------------------------
// SGEMM: C[M,N] = A[M,K] @ B[K,N] + bias  (+residual) (relu)
// BM=BN=128, BK=8, TM=TN=8, 256 threads. All dims divisible by tiles here.
// EPI: 0 = bias, 1 = bias+relu, 2 = bias+residual
// ---------------------------------------------------------------------------
#define BM 128
#define BN 128
#define BKK 8
#define TM 8
#define TN 8

template<int EPI>
__global__ __launch_bounds__(256) void sgemm_k(
    int M, int N, int K,
    const float* __restrict__ A, const float* __restrict__ B,
    const float* __restrict__ bias, const float* __restrict__ R,
    float* __restrict__ C)
{
    __shared__ float As[BKK][BM];
    __shared__ float Bs[BKK][BN];

    const int tid = threadIdx.x;
    const int bx = blockIdx.x, by = blockIdx.y;
    const int tCol = tid & 15;       // 0..15 -> 8 cols each
    const int tRow = tid >> 4;       // 0..15 -> 8 rows each

    const int aRow = tid >> 1;               // 0..127
    const int aCol = (tid & 1) << 2;         // 0 or 4
    const int bRow = tid >> 5;               // 0..7
    const int bCol = (tid & 31) << 2;        // 0..124

    const float* Ab = A + (size_t)(by * BM) * K;
    const float* Bb = B + bx * BN;

    float acc[TM][TN];
#pragma unroll
    for (int i = 0; i < TM; i++)
#pragma unroll
        for (int j = 0; j < TN; j++) acc[i][j] = 0.0f;

    float regM[TM], regN[TN];

    for (int k0 = 0; k0 < K; k0 += BKK) {
        float4 a4 = *(const float4*)(Ab + (size_t)aRow * K + k0 + aCol);
        As[aCol + 0][aRow] = a4.x;
        As[aCol + 1][aRow] = a4.y;
        As[aCol + 2][aRow] = a4.z;
        As[aCol + 3][aRow] = a4.w;
        float4 b4 = *(const float4*)(Bb + (size_t)(k0 + bRow) * N + bCol);
        *(float4*)&Bs[bRow][bCol] = b4;
        __syncthreads();

#pragma unroll
        for (int k = 0; k < BKK; k++) {
#pragma unroll
            for (int i = 0; i < TM; i++) regM[i] = As[k][tRow * TM + i];
#pragma unroll
            for (int j = 0; j < TN; j++) regN[j] = Bs[k][tCol * TN + j];
#pragma unroll
            for (int i = 0; i < TM; i++)
#pragma unroll
                for (int j = 0; j < TN; j++)
                    acc[i][j] += regM[i] * regN[j];
        }
        __syncthreads();
    }

    const int colBase = bx * BN + tCol * TN;
#pragma unroll
    for (int i = 0; i < TM; i++) {
        int row = by * BM + tRow * TM + i;
        float*       Crow = C + (size_t)row * N + colBase;
        const float* Rrow = (EPI == 2) ? (R + (size_t)row * N + colBase) : nullptr;
#pragma unroll
        for (int j = 0; j < TN; j += 4) {
            float4 v;
            v.x = acc[i][j + 0] + bias[colBase + j + 0];
            v.y = acc[i][j + 1] + bias[colBase + j + 1];
            v.z = acc[i][j + 2] + bias[colBase + j + 2];
            v.w = acc[i][j + 3] + bias[colBase + j + 3];
            if (EPI == 2) {
                v.x += Rrow[j + 0]; v.y += Rrow[j + 1];
                v.z += Rrow[j + 2]; v.w += Rrow[j + 3];
            }
            if (EPI == 1) {
                v.x = fmaxf(v.x, 0.0f); v.y = fmaxf(v.y, 0.0f);
                v.z = fmaxf(v.z, 0.0f); v.w = fmaxf(v.w, 0.0f);
            }
            *(float4*)(Crow + j) = v;
        }
    }
}

// ---------------------------------------------------------------------------
// Custom LayerNorm: out = (x - mu) / sqrt(mean((x-mu)^2))   (no eps, no affine)
// One block per row of 768, 256 threads (3 elements/thread).
// ---------------------------------------------------------------------------
__global__ __launch_bounds__(256) void layernorm_k(
    const float* __restrict__ in, float* __restrict__ out)
{
    const int row = blockIdx.x;
    const int t = threadIdx.x;
    const float* x = in + (size_t)row * D_MODEL;
    float v0 = x[t], v1 = x[t + 256], v2 = x[t + 512];

    __shared__ float red[8];

    // --- mean ---
    float s = v0 + v1 + v2;
#pragma unroll
    for (int o = 16; o > 0; o >>= 1) s += __shfl_xor_sync(0xffffffffu, s, o);
    if ((t & 31) == 0) red[t >> 5] = s;
    __syncthreads();
    float mu = (red[0] + red[1] + red[2] + red[3] +
                red[4] + red[5] + red[6] + red[7]) * (1.0f / D_MODEL);
    __syncthreads();

    // --- variance (population) ---
    float d0 = v0 - mu, d1 = v1 - mu, d2 = v2 - mu;
    float q = d0 * d0 + d1 * d1 + d2 * d2;
#pragma unroll
    for (int o = 16; o > 0; o >>= 1) q += __shfl_xor_sync(0xffffffffu, q, o);
    if ((t & 31) == 0) red[t >> 5] = q;
    __syncthreads();
    float msq = (red[0] + red[1] + red[2] + red[3] +
                 red[4] + red[5] + red[6] + red[7]) * (1.0f / D_MODEL);
    float rs = rsqrtf(msq);

    float* y = out + (size_t)row * D_MODEL;
    y[t]       = d0 * rs;
    y[t + 256] = d1 * rs;
    y[t + 512] = d2 * rs;
}

// ---------------------------------------------------------------------------
// Row softmax over VOCAB=8192, in place. One block (512 thr) per row.
// ---------------------------------------------------------------------------
__global__ __launch_bounds__(512) void softmax_k(float* __restrict__ buf)
{
    const int row = blockIdx.x;
    const int t = threadIdx.x;
    float* x = buf + (size_t)row * VOCAB;

    float v[16];
    float mx = -INFINITY;
#pragma unroll
    for (int i = 0; i < 16; i++) {
        v[i] = x[t + i * 512];
        mx = fmaxf(mx, v[i]);
    }
    __shared__ float red[16];
#pragma unroll
    for (int o = 16; o > 0; o >>= 1) mx = fmaxf(mx, __shfl_xor_sync(0xffffffffu, mx, o));
    if ((t & 31) == 0) red[t >> 5] = mx;
    __syncthreads();
    float m = red[0];
#pragma unroll
    for (int w = 1; w < 16; w++) m = fmaxf(m, red[w]);
    __syncthreads();

    float s = 0.0f;
#pragma unroll
    for (int i = 0; i < 16; i++) { v[i] = expf(v[i] - m); s += v[i]; }
#pragma unroll
    for (int o = 16; o > 0; o >>= 1) s += __shfl_xor_sync(0xffffffffu, s, o);
    if ((t & 31) == 0) red[t >> 5] = s;
    __syncthreads();
    float tot = 0.0f;
#pragma unroll
    for (int w = 0; w < 16; w++) tot += red[w];
    float inv = 1.0f / tot;
#pragma unroll
    for (int i = 0; i < 16; i++) x[t + i * 512] = v[i] * inv;
}

// ---------------------------------------------------------------------------
// Launch
// ---------------------------------------------------------------------------
extern "C" void kernel_launch(void* const* d_in, const int* in_sizes, int n_in,
                              void* d_out, int out_size)
{
    // metadata order: X, emb_w, emb_b, Wq, bq, Wk, bk, Wv, bv, Wo, bo,
    //                 W1, b1, W2, b2, Wout, bout
    const float* X     = (const float*)d_in[0];
    const float* emb_w = (const float*)d_in[1];
    const float* emb_b = (const float*)d_in[2];
    // d_in[3..6] (Wq,bq,Wk,bk) are mathematically dead (softmax row-sum == 1)
    const float* Wv    = (const float*)d_in[7];
    const float* bv    = (const float*)d_in[8];
    const float* Wo    = (const float*)d_in[9];
    const float* bo    = (const float*)d_in[10];
    const float* W1    = (const float*)d_in[11];
    const float* b1    = (const float*)d_in[12];
    const float* W2    = (const float*)d_in[13];
    const float* b2    = (const float*)d_in[14];
    const float* Wout  = (const float*)d_in[15];
    const float* bout  = (const float*)d_in[16];
    float* out = (float*)d_out;

    float *pX, *pT1, *pT2, *pH, *pWv;
    cudaGetSymbolAddress((void**)&pX,  g_X);
    cudaGetSymbolAddress((void**)&pT1, g_T1);
    cudaGetSymbolAddress((void**)&pT2, g_T2);
    cudaGetSymbolAddress((void**)&pH,  g_H);
    cudaGetSymbolAddress((void**)&pWv, g_Wv);

    // Repack Wv -> [NB][D][H*DK]
    {
        int n = NBLK * D_MODEL * D_MODEL;
        repack_wv_k<<<(n + 255) / 256, 256>>>(Wv, pWv);
    }

    dim3 blk(256);

    // Embedding: g_X = X @ emb_w + emb_b      [4096,8192]x[8192,768]
    sgemm_k<0><<<dim3(D_MODEL / BN, ROWS / BM), blk>>>(
        ROWS, D_MODEL, VOCAB, X, emb_w, emb_b, nullptr, pX);

    for (int i = 0; i < NBLK; i++) {
        const float* Wv_i = pWv + (size_t)i * D_MODEL * D_MODEL;
        // cat = X @ Wv + bv
        sgemm_k<0><<<dim3(D_MODEL / BN, ROWS / BM), blk>>>(
            ROWS, D_MODEL, D_MODEL, pX, Wv_i, bv + i * D_MODEL, nullptr, pT1);
        // T2 = cat @ Wo + bo + X   (residual fused)
        sgemm_k<2><<<dim3(D_MODEL / BN, ROWS / BM), blk>>>(
            ROWS, D_MODEL, D_MODEL, pT1, Wo + (size_t)i * D_MODEL * D_MODEL,
            bo + i * D_MODEL, pX, pT2);
        // X = LN(T2)
        layernorm_k<<<ROWS, 256>>>(pT2, pX);
        // H = relu(X @ W1 + b1)
        sgemm_k<1><<<dim3(HID / BN, ROWS / BM), blk>>>(
            ROWS, HID, D_MODEL, pX, W1 + (size_t)i * D_MODEL * HID,
            b1 + i * HID, nullptr, pH);
        // T2 = H @ W2 + b2 + X     (residual fused)
        sgemm_k<2><<<dim3(D_MODEL / BN, ROWS / BM), blk>>>(
            ROWS, D_MODEL, HID, pH, W2 + (size_t)i * HID * D_MODEL,
            b2 + i * D_MODEL, pX, pT2);
        // X = LN(T2)
        layernorm_k<<<ROWS, 256>>>(pT2, pX);
    }

    // logits = X @ Wout + bout -> d_out   [4096,768]x[768,8192]
    sgemm_k<0><<<dim3(VOCAB / BN, ROWS / BM), blk>>>(
        ROWS, VOCAB, D_MODEL, pX, Wout, bout, nullptr, out);

    // softmax rows in place
    softmax_k<<<ROWS, 512>>>(out);
}

// round 6
// speedup vs baseline: 2.9640x; 2.9640x over previous
#include <cuda_runtime.h>
#include <cuda_bf16.h>
#include <math.h>
#include <stdint.h>

// ===========================================================================
// TransformerDecoder on GB300 — Round 4: mma.sync tf32 GEMMs (baseline PTX).
//
// tcgen05 is sm_103a-only PTX; this build targets compute_103, so we use the
// family-portable mma.sync.m16n8k8.tf32 path (HMMA on Blackwell).
//
// Math reduction (validated R1): softmax rows sum to 1 => attention == Vv.
// ===========================================================================

#define D_MODEL 768
#define HID     3072
#define VOCAB   8192
#define ROWS    4096
#define NBLK    4

// ---------------------------------------------------------------------------
// Scratch (device globals; runtime allocation forbidden)
// ---------------------------------------------------------------------------
__device__ float g_X  [ROWS * D_MODEL];
__device__ float g_T1 [ROWS * D_MODEL];
__device__ float g_T2 [ROWS * D_MODEL];
__device__ float g_H  [ROWS * HID];
__device__ float g_embT [D_MODEL * VOCAB];          // [N=768, K=8192]
__device__ float g_WvT  [NBLK * D_MODEL * D_MODEL]; // [768,768] per blk (n=h*64+e)
__device__ float g_WoT  [NBLK * D_MODEL * D_MODEL];
__device__ float g_W1T  [NBLK * HID * D_MODEL];     // [3072,768] per blk
__device__ float g_W2T  [NBLK * D_MODEL * HID];     // [768,3072] per blk
__device__ float g_WoutT[VOCAB * D_MODEL];          // [8192,768]

// ---------------------------------------------------------------------------
// Helpers
// ---------------------------------------------------------------------------
__device__ __forceinline__ uint32_t smem_u32(const void* p) {
    uint32_t a;
    asm("{ .reg .u64 t; cvta.to.shared.u64 t, %1; cvt.u32.u64 %0, t; }"
        : "=r"(a) : "l"(p));
    return a;
}
__device__ __forceinline__ void cp16(uint32_t dst, const void* src) {
    asm volatile("cp.async.cg.shared.global [%0], [%1], 16;"
                 :: "r"(dst), "l"(src) : "memory");
}
#define CP_COMMIT() asm volatile("cp.async.commit_group;" ::: "memory")
template<int N> __device__ __forceinline__ void cp_wait() {
    asm volatile("cp.async.wait_group %0;" :: "n"(N) : "memory");
}
__device__ __forceinline__ float rna_tf32(float x) {
    uint32_t u;
    asm("cvt.rna.tf32.f32 %0, %1;" : "=r"(u) : "f"(x));
    return __uint_as_float(u);
}
__device__ __forceinline__ void mma8(float* c, const uint32_t* a, const uint32_t* b) {
    asm volatile("mma.sync.aligned.m16n8k8.row.col.f32.tf32.tf32.f32 "
        "{%0,%1,%2,%3}, {%4,%5,%6,%7}, {%8,%9}, {%0,%1,%2,%3};"
        : "+f"(c[0]), "+f"(c[1]), "+f"(c[2]), "+f"(c[3])
        : "r"(a[0]), "r"(a[1]), "r"(a[2]), "r"(a[3]), "r"(b[0]), "r"(b[1]));
}

// ---------------------------------------------------------------------------
// Batched transpose with RNA tf32 rounding: dst[C,R] = rna(src[R,C]^T)
// grid (ceil(C/32), ceil(R/32), batches), block (32,8)
// ---------------------------------------------------------------------------
__global__ void transpose_rna_k(const float* __restrict__ src, float* __restrict__ dst,
                                int R, int C, long long sstride, long long dstride)
{
    __shared__ float t[32][33];
    const float* s = src + (size_t)blockIdx.z * sstride;
    float* d = dst + (size_t)blockIdx.z * dstride;
    int c0 = blockIdx.x * 32, r0 = blockIdx.y * 32;
#pragma unroll
    for (int dy = 0; dy < 4; dy++) {
        int r = r0 + threadIdx.y + dy * 8, c = c0 + threadIdx.x;
        if (r < R && c < C) t[threadIdx.y + dy * 8][threadIdx.x] = s[(size_t)r * C + c];
    }
    __syncthreads();
#pragma unroll
    for (int dy = 0; dy < 4; dy++) {
        int r = c0 + threadIdx.y + dy * 8, c = r0 + threadIdx.x;
        if (r < C && c < R) d[(size_t)r * R + c] = rna_tf32(t[threadIdx.x][threadIdx.y + dy * 8]);
    }
}

// ---------------------------------------------------------------------------
// tf32 mma GEMM.  C[M,N] = A[M,K] @ B^T, B stored [N,K] K-major.
// CTA 128x128, BK=32, 3-stage cp.async pipeline, 256 threads (8 warps),
// warp tile 64x32. SMEM rows padded to 36 floats => conflict-free LDS.
// EPI: 0=bias, 1=bias+relu, 2=bias+residual. ROUND: rna tf32 outputs.
// ---------------------------------------------------------------------------
#define BM 128
#define BN 128
#define BK 32
#define STAGES 3
#define SROW 36
#define HALF_STAGE (128 * SROW)          // floats (A part)
#define STAGE_F (2 * HALF_STAGE)         // floats per stage (A + B)

template<int EPI, bool ROUND>
__global__ __launch_bounds__(256, 1) void mma_gemm(
    const float* __restrict__ A, const float* __restrict__ B,
    const float* __restrict__ bias, const float* __restrict__ Rres,
    float* __restrict__ C, int N, int K)
{
    extern __shared__ float smemf[];
    const int tid = threadIdx.x;
    const int lane = tid & 31, wid = tid >> 5;
    const int wm = (wid & 1) * 64;           // warp row offset in tile
    const int wn = (wid >> 1) * 32;          // warp col offset in tile
    const int g = lane >> 2, t = lane & 3;

    const int rowA0 = blockIdx.y * BM;
    const int rowB0 = blockIdx.x * BN;

    // cp.async thread mapping: 32 rows x 8 col-chunks per pass, 4 passes
    const int cr = tid >> 3;                 // 0..31
    const int cc = (tid & 7) * 4;            // 0,4,...,28

    const int KT = K / BK;

    float acc[4][4][4];
#pragma unroll
    for (int mt = 0; mt < 4; mt++)
#pragma unroll
        for (int nt = 0; nt < 4; nt++)
#pragma unroll
            for (int j = 0; j < 4; j++) acc[mt][nt][j] = 0.0f;

    auto load_stage = [&](int slot, int kt) {
        float* sA = smemf + slot * STAGE_F;
        float* sB = sA + HALF_STAGE;
        const int k0 = kt * BK + cc;
#pragma unroll
        for (int i = 0; i < 4; i++) {
            int rr = cr + i * 32;
            cp16(smem_u32(&sA[rr * SROW + cc]), A + (size_t)(rowA0 + rr) * K + k0);
            cp16(smem_u32(&sB[rr * SROW + cc]), B + (size_t)(rowB0 + rr) * K + k0);
        }
    };

    // Prefetch STAGES-1 stages
    load_stage(0, 0); CP_COMMIT();
    load_stage(1, 1); CP_COMMIT();

    for (int kt = 0; kt < KT; kt++) {
        int pf = kt + STAGES - 1;
        if (pf < KT) load_stage(pf % STAGES, pf);
        CP_COMMIT();
        cp_wait<STAGES - 1>();
        __syncthreads();

        const float* sA = smemf + (kt % STAGES) * STAGE_F;
        const float* sB = sA + HALF_STAGE;

#pragma unroll
        for (int ks = 0; ks < 4; ks++) {
            const int kk = ks * 8 + t;
            uint32_t af[4][4];
#pragma unroll
            for (int mt = 0; mt < 4; mt++) {
                const float* pa = sA + (wm + mt * 16 + g) * SROW + kk;
                af[mt][0] = __float_as_uint(pa[0]);
                af[mt][2] = __float_as_uint(pa[4]);
                af[mt][1] = __float_as_uint(pa[8 * SROW]);
                af[mt][3] = __float_as_uint(pa[8 * SROW + 4]);
            }
            uint32_t bf[4][2];
#pragma unroll
            for (int nt = 0; nt < 4; nt++) {
                const float* pb = sB + (wn + nt * 8 + g) * SROW + kk;
                bf[nt][0] = __float_as_uint(pb[0]);
                bf[nt][1] = __float_as_uint(pb[4]);
            }
#pragma unroll
            for (int mt = 0; mt < 4; mt++)
#pragma unroll
                for (int nt = 0; nt < 4; nt++)
                    mma8(acc[mt][nt], af[mt], bf[nt]);
        }
        __syncthreads();
    }

    // ------------------------- epilogue -------------------------
#pragma unroll
    for (int mt = 0; mt < 4; mt++) {
#pragma unroll
        for (int nt = 0; nt < 4; nt++) {
            int col = rowB0 + wn + nt * 8 + t * 2;
            float2 b2 = *(const float2*)(bias + col);
#pragma unroll
            for (int h = 0; h < 2; h++) {
                int row = rowA0 + wm + mt * 16 + g + h * 8;
                float2 v;
                v.x = acc[mt][nt][h * 2 + 0] + b2.x;
                v.y = acc[mt][nt][h * 2 + 1] + b2.y;
                if (EPI == 2) {
                    float2 rr = *(const float2*)(Rres + (size_t)row * N + col);
                    v.x += rr.x; v.y += rr.y;
                }
                if (EPI == 1) { v.x = fmaxf(v.x, 0.0f); v.y = fmaxf(v.y, 0.0f); }
                if (ROUND)    { v.x = rna_tf32(v.x);    v.y = rna_tf32(v.y); }
                *(float2*)(C + (size_t)row * N + col) = v;
            }
        }
    }
}

// ---------------------------------------------------------------------------
// Custom LayerNorm (no eps, no affine, population var), RNA-rounded output.
// ---------------------------------------------------------------------------
__global__ __launch_bounds__(256) void layernorm_k(
    const float* __restrict__ in, float* __restrict__ out)
{
    const int row = blockIdx.x;
    const int t = threadIdx.x;
    const float* x = in + (size_t)row * D_MODEL;
    float v0 = x[t], v1 = x[t + 256], v2 = x[t + 512];
    __shared__ float red[8];

    float s = v0 + v1 + v2;
#pragma unroll
    for (int o = 16; o > 0; o >>= 1) s += __shfl_xor_sync(0xffffffffu, s, o);
    if ((t & 31) == 0) red[t >> 5] = s;
    __syncthreads();
    float mu = (red[0] + red[1] + red[2] + red[3] +
                red[4] + red[5] + red[6] + red[7]) * (1.0f / D_MODEL);
    __syncthreads();

    float d0 = v0 - mu, d1 = v1 - mu, d2 = v2 - mu;
    float q = d0 * d0 + d1 * d1 + d2 * d2;
#pragma unroll
    for (int o = 16; o > 0; o >>= 1) q += __shfl_xor_sync(0xffffffffu, q, o);
    if ((t & 31) == 0) red[t >> 5] = q;
    __syncthreads();
    float msq = (red[0] + red[1] + red[2] + red[3] +
                 red[4] + red[5] + red[6] + red[7]) * (1.0f / D_MODEL);
    float rs = rsqrtf(msq);

    float* y = out + (size_t)row * D_MODEL;
    y[t]       = rna_tf32(d0 * rs);
    y[t + 256] = rna_tf32(d1 * rs);
    y[t + 512] = rna_tf32(d2 * rs);
}

// ---------------------------------------------------------------------------
// Row softmax over VOCAB=8192, in place.
// ---------------------------------------------------------------------------
__global__ __launch_bounds__(512) void softmax_k(float* __restrict__ buf)
{
    const int row = blockIdx.x;
    const int t = threadIdx.x;
    float* x = buf + (size_t)row * VOCAB;
    float v[16];
    float mx = -INFINITY;
#pragma unroll
    for (int i = 0; i < 16; i++) { v[i] = x[t + i * 512]; mx = fmaxf(mx, v[i]); }
    __shared__ float red[16];
#pragma unroll
    for (int o = 16; o > 0; o >>= 1) mx = fmaxf(mx, __shfl_xor_sync(0xffffffffu, mx, o));
    if ((t & 31) == 0) red[t >> 5] = mx;
    __syncthreads();
    float m = red[0];
#pragma unroll
    for (int w = 1; w < 16; w++) m = fmaxf(m, red[w]);
    __syncthreads();
    float s = 0.0f;
#pragma unroll
    for (int i = 0; i < 16; i++) { v[i] = expf(v[i] - m); s += v[i]; }
#pragma unroll
    for (int o = 16; o > 0; o >>= 1) s += __shfl_xor_sync(0xffffffffu, s, o);
    if ((t & 31) == 0) red[t >> 5] = s;
    __syncthreads();
    float tot = 0.0f;
#pragma unroll
    for (int w = 0; w < 16; w++) tot += red[w];
    float inv = 1.0f / tot;
#pragma unroll
    for (int i = 0; i < 16; i++) x[t + i * 512] = v[i] * inv;
}

// ---------------------------------------------------------------------------
// Host launch
// ---------------------------------------------------------------------------
extern "C" void kernel_launch(void* const* d_in, const int* in_sizes, int n_in,
                              void* d_out, int out_size)
{
    const float* X     = (const float*)d_in[0];
    const float* emb_w = (const float*)d_in[1];
    const float* emb_b = (const float*)d_in[2];
    // d_in[3..6] (Wq,bq,Wk,bk) dead: softmax row-sum == 1
    const float* Wv    = (const float*)d_in[7];
    const float* bv    = (const float*)d_in[8];
    const float* Wo    = (const float*)d_in[9];
    const float* bo    = (const float*)d_in[10];
    const float* W1    = (const float*)d_in[11];
    const float* b1    = (const float*)d_in[12];
    const float* W2    = (const float*)d_in[13];
    const float* b2    = (const float*)d_in[14];
    const float* Wout  = (const float*)d_in[15];
    const float* bout  = (const float*)d_in[16];
    float* out = (float*)d_out;

    float *pX, *pT1, *pT2, *pH, *pEmbT, *pWvT, *pWoT, *pW1T, *pW2T, *pWoutT;
    cudaGetSymbolAddress((void**)&pX, g_X);
    cudaGetSymbolAddress((void**)&pT1, g_T1);
    cudaGetSymbolAddress((void**)&pT2, g_T2);
    cudaGetSymbolAddress((void**)&pH, g_H);
    cudaGetSymbolAddress((void**)&pEmbT, g_embT);
    cudaGetSymbolAddress((void**)&pWvT, g_WvT);
    cudaGetSymbolAddress((void**)&pWoT, g_WoT);
    cudaGetSymbolAddress((void**)&pW1T, g_W1T);
    cudaGetSymbolAddress((void**)&pW2T, g_W2T);
    cudaGetSymbolAddress((void**)&pWoutT, g_WoutT);

    const int SMEM_SZ = STAGES * STAGE_F * 4;   // 110592 B
    cudaFuncSetAttribute(mma_gemm<0, true >, cudaFuncAttributeMaxDynamicSharedMemorySize, SMEM_SZ);
    cudaFuncSetAttribute(mma_gemm<2, false>, cudaFuncAttributeMaxDynamicSharedMemorySize, SMEM_SZ);
    cudaFuncSetAttribute(mma_gemm<1, true >, cudaFuncAttributeMaxDynamicSharedMemorySize, SMEM_SZ);
    cudaFuncSetAttribute(mma_gemm<0, false>, cudaFuncAttributeMaxDynamicSharedMemorySize, SMEM_SZ);

    dim3 tb(32, 8);
    // Weight transposes (+RNA tf32 rounding). dst[C,R] = src[R,C]^T
    transpose_rna_k<<<dim3(24, 256, 1), tb>>>(emb_w, pEmbT, VOCAB, D_MODEL,
                                              (long long)VOCAB * D_MODEL, (long long)VOCAB * D_MODEL);
    // Wv: per (i,h): [768][64] -> [64][768]; dst rows n=h*64+e match head-concat
    transpose_rna_k<<<dim3(2, 24, NBLK * 12), tb>>>(Wv, pWvT, D_MODEL, 64,
                                                    (long long)D_MODEL * 64, (long long)64 * D_MODEL);
    transpose_rna_k<<<dim3(24, 24, NBLK), tb>>>(Wo, pWoT, D_MODEL, D_MODEL,
                                                (long long)D_MODEL * D_MODEL, (long long)D_MODEL * D_MODEL);
    transpose_rna_k<<<dim3(96, 24, NBLK), tb>>>(W1, pW1T, D_MODEL, HID,
                                                (long long)D_MODEL * HID, (long long)D_MODEL * HID);
    transpose_rna_k<<<dim3(24, 96, NBLK), tb>>>(W2, pW2T, HID, D_MODEL,
                                                (long long)HID * D_MODEL, (long long)HID * D_MODEL);
    transpose_rna_k<<<dim3(256, 24, 1), tb>>>(Wout, pWoutT, D_MODEL, VOCAB,
                                              (long long)D_MODEL * VOCAB, (long long)D_MODEL * VOCAB);

    // emb: g_X = X @ emb_w + emb_b
    mma_gemm<0, true><<<dim3(D_MODEL / BN, ROWS / BM), 256, SMEM_SZ>>>(
        X, pEmbT, emb_b, nullptr, pX, D_MODEL, VOCAB);

    for (int i = 0; i < NBLK; i++) {
        mma_gemm<0, true><<<dim3(D_MODEL / BN, ROWS / BM), 256, SMEM_SZ>>>(
            pX, pWvT + (size_t)i * D_MODEL * D_MODEL, bv + i * D_MODEL, nullptr,
            pT1, D_MODEL, D_MODEL);
        mma_gemm<2, false><<<dim3(D_MODEL / BN, ROWS / BM), 256, SMEM_SZ>>>(
            pT1, pWoT + (size_t)i * D_MODEL * D_MODEL, bo + i * D_MODEL, pX,
            pT2, D_MODEL, D_MODEL);
        layernorm_k<<<ROWS, 256>>>(pT2, pX);
        mma_gemm<1, true><<<dim3(HID / BN, ROWS / BM), 256, SMEM_SZ>>>(
            pX, pW1T + (size_t)i * HID * D_MODEL, b1 + i * HID, nullptr,
            pH, HID, D_MODEL);
        mma_gemm<2, false><<<dim3(D_MODEL / BN, ROWS / BM), 256, SMEM_SZ>>>(
            pH, pW2T + (size_t)i * D_MODEL * HID, b2 + i * D_MODEL, pX,
            pT2, D_MODEL, HID);
        layernorm_k<<<ROWS, 256>>>(pT2, pX);
    }

    // logits: out = g_X @ Wout + bout
    mma_gemm<0, false><<<dim3(VOCAB / BN, ROWS / BM), 256, SMEM_SZ>>>(
        pX, pWoutT, bout, nullptr, out, VOCAB, D_MODEL);

    softmax_k<<<ROWS, 512>>>(out);
}

// round 8
// speedup vs baseline: 6.3502x; 2.1425x over previous
#include <cuda_runtime.h>
#include <cuda_fp16.h>
#include <math.h>
#include <stdint.h>

// ===========================================================================
// TransformerDecoder on GB300 — Round 7 (re-bench of R6; infra failed last
// round): mma.sync m16n8k16 fp16 GEMMs.
//
// Math reduction (validated): softmax rows sum to 1 => attention == Vv.
// fp16 mantissa == tf32 mantissa (10 bits); fp32 accumulate => same accuracy
// class as the passing tf32 kernel, at ~2x tensor rate and half the traffic.
//
// Narrow GEMMs (N=768) use split-K x2 (fp32 partials) to fix the 2-wave tail;
// the partial reduction is fused with bias / residual+LayerNorm.
// ===========================================================================

#define D_MODEL 768
#define HID     3072
#define VOCAB   8192
#define ROWS    4096
#define NBLK    4

// ---------------------------------------------------------------------------
// Scratch (device globals; runtime allocation forbidden)
// ---------------------------------------------------------------------------
__device__ __half g_hXin[ROWS * VOCAB];             // fp16 copy of input X
__device__ __half g_hX  [ROWS * D_MODEL];           // current activations
__device__ __half g_hT1 [ROWS * D_MODEL];           // V-proj output
__device__ __half g_hH  [ROWS * HID];               // FFN hidden
__device__ float  g_P   [2 * ROWS * D_MODEL];       // split-K fp32 partials
__device__ __half g_embT [D_MODEL * VOCAB];         // [768, 8192]
__device__ __half g_WvT  [NBLK * D_MODEL * D_MODEL];
__device__ __half g_WoT  [NBLK * D_MODEL * D_MODEL];
__device__ __half g_W1T  [NBLK * HID * D_MODEL];    // [3072, 768] per blk
__device__ __half g_W2T  [NBLK * D_MODEL * HID];    // [768, 3072] per blk
__device__ __half g_WoutT[VOCAB * D_MODEL];         // [8192, 768]

// ---------------------------------------------------------------------------
// Helpers
// ---------------------------------------------------------------------------
__device__ __forceinline__ uint32_t smem_u32(const void* p) {
    uint32_t a;
    asm("{ .reg .u64 t; cvta.to.shared.u64 t, %1; cvt.u32.u64 %0, t; }"
        : "=r"(a) : "l"(p));
    return a;
}
__device__ __forceinline__ void cp16(uint32_t dst, const void* src) {
    asm volatile("cp.async.cg.shared.global [%0], [%1], 16;"
                 :: "r"(dst), "l"(src) : "memory");
}
#define CP_COMMIT() asm volatile("cp.async.commit_group;" ::: "memory")
template<int N> __device__ __forceinline__ void cp_wait() {
    asm volatile("cp.async.wait_group %0;" :: "n"(N) : "memory");
}
__device__ __forceinline__ void mma16(float* c, const uint32_t* a, const uint32_t* b) {
    asm volatile("mma.sync.aligned.m16n8k16.row.col.f32.f16.f16.f32 "
        "{%0,%1,%2,%3}, {%4,%5,%6,%7}, {%8,%9}, {%0,%1,%2,%3};"
        : "+f"(c[0]), "+f"(c[1]), "+f"(c[2]), "+f"(c[3])
        : "r"(a[0]), "r"(a[1]), "r"(a[2]), "r"(a[3]), "r"(b[0]), "r"(b[1]));
}

// ---------------------------------------------------------------------------
// fp32 -> fp16 batched transpose: dst[C,R] = half(src[R,C]^T)
// grid (ceil(C/32), ceil(R/32), batches), block (32,8)
// ---------------------------------------------------------------------------
__global__ void transpose_h_k(const float* __restrict__ src, __half* __restrict__ dst,
                              int R, int C, long long sstride, long long dstride)
{
    __shared__ float t[32][33];
    const float* s = src + (size_t)blockIdx.z * sstride;
    __half* d = dst + (size_t)blockIdx.z * dstride;
    int c0 = blockIdx.x * 32, r0 = blockIdx.y * 32;
#pragma unroll
    for (int dy = 0; dy < 4; dy++) {
        int r = r0 + threadIdx.y + dy * 8, c = c0 + threadIdx.x;
        if (r < R && c < C) t[threadIdx.y + dy * 8][threadIdx.x] = s[(size_t)r * C + c];
    }
    __syncthreads();
#pragma unroll
    for (int dy = 0; dy < 4; dy++) {
        int r = c0 + threadIdx.y + dy * 8, c = r0 + threadIdx.x;
        if (r < C && c < R)
            d[(size_t)r * R + c] = __float2half_rn(t[threadIdx.x][threadIdx.y + dy * 8]);
    }
}

// fp32 -> fp16 elementwise (for the harness input X)
__global__ void cvt_h_k(const float* __restrict__ src, __half* __restrict__ dst, int n2)
{
    int i = blockIdx.x * blockDim.x + threadIdx.x;
    if (i >= n2) return;
    float2 v = *(const float2*)(src + 2 * i);
    *(__half2*)(dst + 2 * i) = __floats2half2_rn(v.x, v.y);
}

// ---------------------------------------------------------------------------
// fp16 mma GEMM.  C[M,N] = A[M,K] @ B^T, B stored [N,K] K-major, fp16.
// CTA 128 x BN, BK=64 halves, 3-stage cp.async, 256 threads (8 warps).
// BN=128: warp tile 64x32 (NT=4).  BN=256: warp tile 64x64 (NT=8).
// SMEM rows padded to 36 words (64 halves + 8 pad) => conflict-free LDS.
// EPI: 1 = bias+relu -> half, 2 = raw fp32 split partial (z = blockIdx.z),
//      3 = bias -> fp32.
// ---------------------------------------------------------------------------
#define BK 64
#define STAGES 3
#define SROWW 36

template<int BN, int EPI>
__global__ __launch_bounds__(256, 1) void hgemm(
    const __half* __restrict__ A, const __half* __restrict__ B,
    const float* __restrict__ bias, void* __restrict__ Cout,
    float* __restrict__ P, int N, int K_in)
{
    constexpr int WN = BN / 4;
    constexpr int NT = WN / 8;
    constexpr int A_WORDS = 128 * SROWW;
    constexpr int B_WORDS = BN * SROWW;
    constexpr int STAGE_W = A_WORDS + B_WORDS;
    extern __shared__ float smemf[];

    const int tid = threadIdx.x;
    const int lane = tid & 31, wid = tid >> 5;
    const int wm = (wid & 1) * 64;
    const int wn = (wid >> 1) * WN;
    const int g = lane >> 2, tt = lane & 3;

    const int rowA0 = blockIdx.y * 128;
    const int rowB0 = blockIdx.x * BN;

    const int K    = (EPI == 2) ? (K_in >> 1) : K_in;
    const int koff = (EPI == 2) ? (int)blockIdx.z * K : 0;
    const __half* Ab = A + (size_t)rowA0 * K_in + koff;
    const __half* Bb = B + (size_t)rowB0 * K_in + koff;

    const int cr = tid >> 3;          // 0..31
    const int cch = (tid & 7) * 8;    // half offset 0..56
    const int ccw = cch >> 1;         // word offset

    const int KT = K / BK;

    float acc[4][NT][4];
#pragma unroll
    for (int mt = 0; mt < 4; mt++)
#pragma unroll
        for (int nt = 0; nt < NT; nt++)
#pragma unroll
            for (int j = 0; j < 4; j++) acc[mt][nt][j] = 0.0f;

    auto load_stage = [&](int slot, int kt) {
        float* sA = smemf + slot * STAGE_W;
        float* sB = sA + A_WORDS;
        const int k0 = kt * BK + cch;
#pragma unroll
        for (int i = 0; i < 4; i++) {
            int rr = cr + i * 32;
            cp16(smem_u32(&sA[rr * SROWW + ccw]), Ab + (size_t)rr * K_in + k0);
        }
#pragma unroll
        for (int i = 0; i < BN / 32; i++) {
            int rr = cr + i * 32;
            cp16(smem_u32(&sB[rr * SROWW + ccw]), Bb + (size_t)rr * K_in + k0);
        }
    };

    load_stage(0, 0); CP_COMMIT();
    load_stage(1, 1); CP_COMMIT();

    for (int kt = 0; kt < KT; kt++) {
        int pf = kt + STAGES - 1;
        if (pf < KT) load_stage(pf % STAGES, pf);
        CP_COMMIT();
        cp_wait<STAGES - 1>();
        __syncthreads();

        const float* sA = smemf + (kt % STAGES) * STAGE_W;
        const float* sB = sA + A_WORDS;

#pragma unroll
        for (int ks = 0; ks < 4; ks++) {
            const int kw = ks * 8 + tt;
            uint32_t af[4][4];
#pragma unroll
            for (int mt = 0; mt < 4; mt++) {
                const float* pa = sA + (wm + mt * 16 + g) * SROWW + kw;
                af[mt][0] = __float_as_uint(pa[0]);
                af[mt][1] = __float_as_uint(pa[8 * SROWW]);
                af[mt][2] = __float_as_uint(pa[4]);
                af[mt][3] = __float_as_uint(pa[8 * SROWW + 4]);
            }
            uint32_t bf[NT][2];
#pragma unroll
            for (int nt = 0; nt < NT; nt++) {
                const float* pb = sB + (wn + nt * 8 + g) * SROWW + kw;
                bf[nt][0] = __float_as_uint(pb[0]);
                bf[nt][1] = __float_as_uint(pb[4]);
            }
#pragma unroll
            for (int mt = 0; mt < 4; mt++)
#pragma unroll
                for (int nt = 0; nt < NT; nt++)
                    mma16(acc[mt][nt], af[mt], bf[nt]);
        }
        __syncthreads();
    }

    // ------------------------- epilogue -------------------------
#pragma unroll
    for (int mt = 0; mt < 4; mt++) {
#pragma unroll
        for (int nt = 0; nt < NT; nt++) {
            const int col = rowB0 + wn + nt * 8 + tt * 2;
            if (EPI == 2) {
                float* Pz = P + (size_t)blockIdx.z * ROWS * N;
#pragma unroll
                for (int h = 0; h < 2; h++) {
                    int row = rowA0 + wm + mt * 16 + g + h * 8;
                    float2 v = {acc[mt][nt][h * 2], acc[mt][nt][h * 2 + 1]};
                    *(float2*)(Pz + (size_t)row * N + col) = v;
                }
            } else {
                float2 bb = *(const float2*)(bias + col);
#pragma unroll
                for (int h = 0; h < 2; h++) {
                    int row = rowA0 + wm + mt * 16 + g + h * 8;
                    float x = acc[mt][nt][h * 2] + bb.x;
                    float y = acc[mt][nt][h * 2 + 1] + bb.y;
                    if (EPI == 1) { x = fmaxf(x, 0.0f); y = fmaxf(y, 0.0f); }
                    if (EPI == 3) {
                        *(float2*)((float*)Cout + (size_t)row * N + col) = make_float2(x, y);
                    } else {
                        *(__half2*)((__half*)Cout + (size_t)row * N + col) =
                            __floats2half2_rn(x, y);
                    }
                }
            }
        }
    }
}

// ---------------------------------------------------------------------------
// Split-K reduce: out_half = half(P0 + P1 + bias)
// ---------------------------------------------------------------------------
__global__ __launch_bounds__(256) void reduce_half_k(
    const float* __restrict__ P, const float* __restrict__ bias,
    __half* __restrict__ out)
{
    int i = blockIdx.x * blockDim.x + threadIdx.x;      // over ROWS*768/2
    int idx = i * 2;
    int col = idx % D_MODEL;
    float2 p0 = *(const float2*)(P + idx);
    float2 p1 = *(const float2*)(P + (size_t)ROWS * D_MODEL + idx);
    float2 bb = *(const float2*)(bias + col);
    *(__half2*)(out + idx) = __floats2half2_rn(p0.x + p1.x + bb.x, p0.y + p1.y + bb.y);
}

// ---------------------------------------------------------------------------
// Split-K reduce + residual + custom LayerNorm (no eps, population var):
//   X = half( LN(P0 + P1 + bias + res) ).   One block per row. In-place OK.
// ---------------------------------------------------------------------------
__global__ __launch_bounds__(256) void ln_reduce_k(
    const float* __restrict__ P, const float* __restrict__ bias,
    const __half* __restrict__ res, __half* __restrict__ out)
{
    const int row = blockIdx.x;
    const int t = threadIdx.x;
    const size_t base = (size_t)row * D_MODEL;
    const float* P1 = P + (size_t)ROWS * D_MODEL;

    float v0 = P[base + t]       + P1[base + t]       + bias[t]
             + __half2float(res[base + t]);
    float v1 = P[base + t + 256] + P1[base + t + 256] + bias[t + 256]
             + __half2float(res[base + t + 256]);
    float v2 = P[base + t + 512] + P1[base + t + 512] + bias[t + 512]
             + __half2float(res[base + t + 512]);

    __shared__ float red[8];
    float s = v0 + v1 + v2;
#pragma unroll
    for (int o = 16; o > 0; o >>= 1) s += __shfl_xor_sync(0xffffffffu, s, o);
    if ((t & 31) == 0) red[t >> 5] = s;
    __syncthreads();
    float mu = (red[0] + red[1] + red[2] + red[3] +
                red[4] + red[5] + red[6] + red[7]) * (1.0f / D_MODEL);
    __syncthreads();

    float d0 = v0 - mu, d1 = v1 - mu, d2 = v2 - mu;
    float q = d0 * d0 + d1 * d1 + d2 * d2;
#pragma unroll
    for (int o = 16; o > 0; o >>= 1) q += __shfl_xor_sync(0xffffffffu, q, o);
    if ((t & 31) == 0) red[t >> 5] = q;
    __syncthreads();
    float msq = (red[0] + red[1] + red[2] + red[3] +
                 red[4] + red[5] + red[6] + red[7]) * (1.0f / D_MODEL);
    float rs = rsqrtf(msq);

    out[base + t]       = __float2half_rn(d0 * rs);
    out[base + t + 256] = __float2half_rn(d1 * rs);
    out[base + t + 512] = __float2half_rn(d2 * rs);
}

// ---------------------------------------------------------------------------
// Row softmax over VOCAB=8192, in place (fp32).
// ---------------------------------------------------------------------------
__global__ __launch_bounds__(512) void softmax_k(float* __restrict__ buf)
{
    const int row = blockIdx.x;
    const int t = threadIdx.x;
    float* x = buf + (size_t)row * VOCAB;
    float v[16];
    float mx = -INFINITY;
#pragma unroll
    for (int i = 0; i < 16; i++) { v[i] = x[t + i * 512]; mx = fmaxf(mx, v[i]); }
    __shared__ float red[16];
#pragma unroll
    for (int o = 16; o > 0; o >>= 1) mx = fmaxf(mx, __shfl_xor_sync(0xffffffffu, mx, o));
    if ((t & 31) == 0) red[t >> 5] = mx;
    __syncthreads();
    float m = red[0];
#pragma unroll
    for (int w = 1; w < 16; w++) m = fmaxf(m, red[w]);
    __syncthreads();
    float s = 0.0f;
#pragma unroll
    for (int i = 0; i < 16; i++) { v[i] = expf(v[i] - m); s += v[i]; }
#pragma unroll
    for (int o = 16; o > 0; o >>= 1) s += __shfl_xor_sync(0xffffffffu, s, o);
    if ((t & 31) == 0) red[t >> 5] = s;
    __syncthreads();
    float tot = 0.0f;
#pragma unroll
    for (int w = 0; w < 16; w++) tot += red[w];
    float inv = 1.0f / tot;
#pragma unroll
    for (int i = 0; i < 16; i++) x[t + i * 512] = v[i] * inv;
}

// ---------------------------------------------------------------------------
// Host launch
// ---------------------------------------------------------------------------
extern "C" void kernel_launch(void* const* d_in, const int* in_sizes, int n_in,
                              void* d_out, int out_size)
{
    const float* X     = (const float*)d_in[0];
    const float* emb_w = (const float*)d_in[1];
    const float* emb_b = (const float*)d_in[2];
    // d_in[3..6] (Wq,bq,Wk,bk) dead: softmax row-sum == 1
    const float* Wv    = (const float*)d_in[7];
    const float* bv    = (const float*)d_in[8];
    const float* Wo    = (const float*)d_in[9];
    const float* bo    = (const float*)d_in[10];
    const float* W1    = (const float*)d_in[11];
    const float* b1    = (const float*)d_in[12];
    const float* W2    = (const float*)d_in[13];
    const float* b2    = (const float*)d_in[14];
    const float* Wout  = (const float*)d_in[15];
    const float* bout  = (const float*)d_in[16];
    float* out = (float*)d_out;

    __half *pXin, *pHX, *pHT1, *pHH, *pEmbT, *pWvT, *pWoT, *pW1T, *pW2T, *pWoutT;
    float* pP;
    cudaGetSymbolAddress((void**)&pXin, g_hXin);
    cudaGetSymbolAddress((void**)&pHX, g_hX);
    cudaGetSymbolAddress((void**)&pHT1, g_hT1);
    cudaGetSymbolAddress((void**)&pHH, g_hH);
    cudaGetSymbolAddress((void**)&pP, g_P);
    cudaGetSymbolAddress((void**)&pEmbT, g_embT);
    cudaGetSymbolAddress((void**)&pWvT, g_WvT);
    cudaGetSymbolAddress((void**)&pWoT, g_WoT);
    cudaGetSymbolAddress((void**)&pW1T, g_W1T);
    cudaGetSymbolAddress((void**)&pW2T, g_W2T);
    cudaGetSymbolAddress((void**)&pWoutT, g_WoutT);

    const int SM128 = STAGES * (128 + 128) * SROWW * 4;   // 110592 B
    const int SM256 = STAGES * (128 + 256) * SROWW * 4;   // 165888 B
    cudaFuncSetAttribute(hgemm<128, 2>, cudaFuncAttributeMaxDynamicSharedMemorySize, SM128);
    cudaFuncSetAttribute(hgemm<256, 1>, cudaFuncAttributeMaxDynamicSharedMemorySize, SM256);
    cudaFuncSetAttribute(hgemm<256, 3>, cudaFuncAttributeMaxDynamicSharedMemorySize, SM256);

    // --- input conversion + weight transposes (fp32 -> fp16) ---
    cvt_h_k<<<(ROWS * VOCAB / 2 + 255) / 256, 256>>>(X, pXin, ROWS * VOCAB / 2);
    dim3 tb(32, 8);
    transpose_h_k<<<dim3(24, 256, 1), tb>>>(emb_w, pEmbT, VOCAB, D_MODEL,
                                            (long long)VOCAB * D_MODEL, (long long)VOCAB * D_MODEL);
    // Wv per (i,h): [768][64] -> [64][768]; dst rows n=h*64+e match head-concat
    transpose_h_k<<<dim3(2, 24, NBLK * 12), tb>>>(Wv, pWvT, D_MODEL, 64,
                                                  (long long)D_MODEL * 64, (long long)64 * D_MODEL);
    transpose_h_k<<<dim3(24, 24, NBLK), tb>>>(Wo, pWoT, D_MODEL, D_MODEL,
                                              (long long)D_MODEL * D_MODEL, (long long)D_MODEL * D_MODEL);
    transpose_h_k<<<dim3(96, 24, NBLK), tb>>>(W1, pW1T, D_MODEL, HID,
                                              (long long)D_MODEL * HID, (long long)D_MODEL * HID);
    transpose_h_k<<<dim3(24, 96, NBLK), tb>>>(W2, pW2T, HID, D_MODEL,
                                              (long long)HID * D_MODEL, (long long)HID * D_MODEL);
    transpose_h_k<<<dim3(256, 24, 1), tb>>>(Wout, pWoutT, D_MODEL, VOCAB,
                                            (long long)D_MODEL * VOCAB, (long long)D_MODEL * VOCAB);

    const int RED_BLKS = ROWS * D_MODEL / 2 / 256;   // 6144

    // emb (split-K x2): P = Xin @ embT^T ; X = half(P0+P1+emb_b)
    hgemm<128, 2><<<dim3(6, 32, 2), 256, SM128>>>(
        pXin, pEmbT, nullptr, nullptr, pP, D_MODEL, VOCAB);
    reduce_half_k<<<RED_BLKS, 256>>>(pP, emb_b, pHX);

    for (int i = 0; i < NBLK; i++) {
        // Vproj (split): T1 = half(P0+P1+bv)
        hgemm<128, 2><<<dim3(6, 32, 2), 256, SM128>>>(
            pHX, pWvT + (size_t)i * D_MODEL * D_MODEL, nullptr, nullptr, pP,
            D_MODEL, D_MODEL);
        reduce_half_k<<<RED_BLKS, 256>>>(pP, bv + i * D_MODEL, pHT1);
        // Oproj (split) + fused residual+LN: X = half(LN(P0+P1+bo+X))
        hgemm<128, 2><<<dim3(6, 32, 2), 256, SM128>>>(
            pHT1, pWoT + (size_t)i * D_MODEL * D_MODEL, nullptr, nullptr, pP,
            D_MODEL, D_MODEL);
        ln_reduce_k<<<ROWS, 256>>>(pP, bo + i * D_MODEL, pHX, pHX);
        // FFN1: H = half(relu(X @ W1 + b1))
        hgemm<256, 1><<<dim3(HID / 256, 32), 256, SM256>>>(
            pHX, pW1T + (size_t)i * HID * D_MODEL, b1 + i * HID, pHH, nullptr,
            HID, D_MODEL);
        // FFN2 (split) + fused residual+LN
        hgemm<128, 2><<<dim3(6, 32, 2), 256, SM128>>>(
            pHH, pW2T + (size_t)i * D_MODEL * HID, nullptr, nullptr, pP,
            D_MODEL, HID);
        ln_reduce_k<<<ROWS, 256>>>(pP, b2 + i * D_MODEL, pHX, pHX);
    }

    // logits: out = X @ Wout + bout (fp32), then softmax
    hgemm<256, 3><<<dim3(VOCAB / 256, 32), 256, SM256>>>(
        pHX, pWoutT, bout, out, nullptr, VOCAB, D_MODEL);
    softmax_k<<<ROWS, 512>>>(out);
}